// round 3
// baseline (speedup 1.0000x reference)
#include <cuda_runtime.h>
#include <math.h>

#define HDIM 4096
#define IDIM 4096
#define TPB  256
#define GRID 592      // 4 * 148; single resident wave on 148- or 152-SM parts
#define MAXROWS 7     // ceil(4096 / 592)

__global__ __launch_bounds__(TPB, 4) void slstm_pers_kernel(
    const float* __restrict__ x,
    const float* __restrict__ h_prev,
    const float* __restrict__ c_prev,
    const float* __restrict__ n_prev,
    const float* __restrict__ m_prev,
    const float* __restrict__ w_i,
    const float* __restrict__ w_f,
    const float* __restrict__ w_o,
    const float* __restrict__ w_z,
    const float* __restrict__ r_i,
    const float* __restrict__ r_f,
    const float* __restrict__ r_o,
    const float* __restrict__ r_z,
    const float* __restrict__ b_i,
    const float* __restrict__ b_f,
    const float* __restrict__ b_o,
    const float* __restrict__ b_z,
    float* __restrict__ out)
{
    const int tid  = threadIdx.x;
    const int lane = tid & 31;
    const int warp = tid >> 5;

    // warp -> gate matrix (0..3 use x, 4..7 use h_prev)
    const float* mat;
    switch (warp) {
        case 0:  mat = w_i; break;
        case 1:  mat = w_f; break;
        case 2:  mat = w_o; break;
        case 3:  mat = w_z; break;
        case 4:  mat = r_i; break;
        case 5:  mat = r_f; break;
        case 6:  mat = r_o; break;
        default: mat = r_z; break;
    }
    const float4* src4 = (const float4*)((warp < 4) ? x : h_prev);

    __shared__ float pre[MAXROWS][8];

    int row = blockIdx.x;
    int j = 0;
    while (row < HDIM) {
        const float4* m4 = (const float4*)(mat + (size_t)row * IDIM);

        float acc0 = 0.0f, acc1 = 0.0f;
        // 1024 float4 per row / 32 lanes = 32 float4 per lane, in 8 batches of 4
#pragma unroll
        for (int b = 0; b < 8; ++b) {
            const int base = b * 128 + lane;
            // front-batched weight loads (streaming, evict-first)
            float4 w0 = __ldcs(m4 + base);
            float4 w1 = __ldcs(m4 + base + 32);
            float4 w2 = __ldcs(m4 + base + 64);
            float4 w3 = __ldcs(m4 + base + 96);
            // vector operand (L1-resident after first row)
            float4 s0 = __ldg(src4 + base);
            float4 s1 = __ldg(src4 + base + 32);
            float4 s2 = __ldg(src4 + base + 64);
            float4 s3 = __ldg(src4 + base + 96);

            acc0 += w0.x * s0.x + w0.y * s0.y + w0.z * s0.z + w0.w * s0.w;
            acc1 += w1.x * s1.x + w1.y * s1.y + w1.z * s1.z + w1.w * s1.w;
            acc0 += w2.x * s2.x + w2.y * s2.y + w2.z * s2.z + w2.w * s2.w;
            acc1 += w3.x * s3.x + w3.y * s3.y + w3.z * s3.z + w3.w * s3.w;
        }
        float acc = acc0 + acc1;

#pragma unroll
        for (int s = 16; s > 0; s >>= 1)
            acc += __shfl_xor_sync(0xFFFFFFFFu, acc, s);
        if (lane == 0) pre[j][warp] = acc;

        row += GRID;
        ++j;
    }
    __syncthreads();

    // gating: thread t handles this CTA's t-th row (t < nrows <= 7)
    const int r = blockIdx.x + tid * GRID;
    if (tid < MAXROWS && r < HDIM) {
        float i_t = pre[tid][0] + pre[tid][4] + __ldg(b_i + r);
        float f_t = pre[tid][1] + pre[tid][5] + __ldg(b_f + r);
        float o_t = pre[tid][2] + pre[tid][6] + __ldg(b_o + r);
        float z_t = pre[tid][3] + pre[tid][7] + __ldg(b_z + r);

        float mp = __ldg(m_prev + r);
        float cp = __ldg(c_prev + r);
        float np = __ldg(n_prev + r);

        // stable log_sigmoid(f) = min(f,0) - log1p(exp(-|f|))
        float log_f = fminf(f_t, 0.0f) - log1pf(expf(-fabsf(f_t)));
        float m_t = fmaxf(log_f + mp, i_t);
        float i_p = expf(i_t - m_t);
        float f_p = expf(log_f + mp - m_t);
        float c_t = f_p * cp + i_p * tanhf(z_t);
        float n_t = f_p * np + i_p;
        float sig_o = 1.0f / (1.0f + expf(-o_t));
        float h_t = sig_o * tanhf(c_t / n_t);

        out[r]            = h_t;
        out[HDIM + r]     = c_t;
        out[2 * HDIM + r] = n_t;
        out[3 * HDIM + r] = m_t;
    }
}

extern "C" void kernel_launch(void* const* d_in, const int* in_sizes, int n_in,
                              void* d_out, int out_size)
{
    const float* x      = (const float*)d_in[0];
    const float* h_prev = (const float*)d_in[1];
    const float* c_prev = (const float*)d_in[2];
    const float* n_prev = (const float*)d_in[3];
    const float* m_prev = (const float*)d_in[4];
    const float* w_i    = (const float*)d_in[5];
    const float* w_f    = (const float*)d_in[6];
    const float* w_o    = (const float*)d_in[7];
    const float* w_z    = (const float*)d_in[8];
    const float* r_i    = (const float*)d_in[9];
    const float* r_f    = (const float*)d_in[10];
    const float* r_o    = (const float*)d_in[11];
    const float* r_z    = (const float*)d_in[12];
    const float* b_i    = (const float*)d_in[13];
    const float* b_f    = (const float*)d_in[14];
    const float* b_o    = (const float*)d_in[15];
    const float* b_z    = (const float*)d_in[16];
    float* out = (float*)d_out;

    slstm_pers_kernel<<<GRID, TPB>>>(x, h_prev, c_prev, n_prev, m_prev,
                                     w_i, w_f, w_o, w_z,
                                     r_i, r_f, r_o, r_z,
                                     b_i, b_f, b_o, b_z, out);
}

// round 4
// speedup vs baseline: 1.2207x; 1.2207x over previous
#include <cuda_runtime.h>
#include <math.h>

#define HDIM 4096
#define IDIM 4096
#define TPB  256
#define NWARP (TPB / 32)
#define GRID 592          // ~4 CTAs/SM, single resident wave
#define MAXROWS 7         // ceil(4096 / 592)

__global__ __launch_bounds__(TPB, 4) void slstm_pers2_kernel(
    const float* __restrict__ x,
    const float* __restrict__ h_prev,
    const float* __restrict__ c_prev,
    const float* __restrict__ n_prev,
    const float* __restrict__ m_prev,
    const float* __restrict__ w_i,
    const float* __restrict__ w_f,
    const float* __restrict__ w_o,
    const float* __restrict__ w_z,
    const float* __restrict__ r_i,
    const float* __restrict__ r_f,
    const float* __restrict__ r_o,
    const float* __restrict__ r_z,
    const float* __restrict__ b_i,
    const float* __restrict__ b_f,
    const float* __restrict__ b_o,
    const float* __restrict__ b_z,
    float* __restrict__ out)
{
    const int tid  = threadIdx.x;
    const int lane = tid & 31;
    const int warp = tid >> 5;

    const float4* xv4 = (const float4*)x;
    const float4* hv4 = (const float4*)h_prev;

    // [row-slot][warp][gate] warp-level partials
    __shared__ float red[MAXROWS][NWARP][8];
    // [row-slot][gate] cross-warp totals
    __shared__ float tot[MAXROWS][8];

    int row = blockIdx.x;
    int j = 0;
    for (; row < HDIM; row += GRID, ++j) {
        const size_t roff = (size_t)row * IDIM;
        const float4* W0 = (const float4*)(w_i + roff);
        const float4* W1 = (const float4*)(w_f + roff);
        const float4* W2 = (const float4*)(w_o + roff);
        const float4* W3 = (const float4*)(w_z + roff);
        const float4* R0 = (const float4*)(r_i + roff);
        const float4* R1 = (const float4*)(r_f + roff);
        const float4* R2 = (const float4*)(r_o + roff);
        const float4* R3 = (const float4*)(r_z + roff);

        float accA[8], accB[8];
#pragma unroll
        for (int g = 0; g < 8; ++g) { accA[g] = 0.0f; accB[g] = 0.0f; }

#pragma unroll
        for (int blk = 0; blk < 2; ++blk) {
            const int ka = (2 * blk + 0) * TPB + tid;
            const int kb = (2 * blk + 1) * TPB + tid;

            // ---- front-batched loads (20 x LDG.128) ----
            float4 xa = __ldg(xv4 + ka);
            float4 ha = __ldg(hv4 + ka);
            float4 xb = __ldg(xv4 + kb);
            float4 hb = __ldg(hv4 + kb);

            float4 a0 = __ldcs(W0 + ka);
            float4 a1 = __ldcs(W1 + ka);
            float4 a2 = __ldcs(W2 + ka);
            float4 a3 = __ldcs(W3 + ka);
            float4 c0 = __ldcs(R0 + ka);
            float4 c1 = __ldcs(R1 + ka);
            float4 c2 = __ldcs(R2 + ka);
            float4 c3 = __ldcs(R3 + ka);

            float4 d0 = __ldcs(W0 + kb);
            float4 d1 = __ldcs(W1 + kb);
            float4 d2 = __ldcs(W2 + kb);
            float4 d3 = __ldcs(W3 + kb);
            float4 e0 = __ldcs(R0 + kb);
            float4 e1 = __ldcs(R1 + kb);
            float4 e2 = __ldcs(R2 + kb);
            float4 e3 = __ldcs(R3 + kb);

            // ---- compute ----
            accA[0] += a0.x * xa.x + a0.y * xa.y + a0.z * xa.z + a0.w * xa.w;
            accA[1] += a1.x * xa.x + a1.y * xa.y + a1.z * xa.z + a1.w * xa.w;
            accA[2] += a2.x * xa.x + a2.y * xa.y + a2.z * xa.z + a2.w * xa.w;
            accA[3] += a3.x * xa.x + a3.y * xa.y + a3.z * xa.z + a3.w * xa.w;
            accA[4] += c0.x * ha.x + c0.y * ha.y + c0.z * ha.z + c0.w * ha.w;
            accA[5] += c1.x * ha.x + c1.y * ha.y + c1.z * ha.z + c1.w * ha.w;
            accA[6] += c2.x * ha.x + c2.y * ha.y + c2.z * ha.z + c2.w * ha.w;
            accA[7] += c3.x * ha.x + c3.y * ha.y + c3.z * ha.z + c3.w * ha.w;

            accB[0] += d0.x * xb.x + d0.y * xb.y + d0.z * xb.z + d0.w * xb.w;
            accB[1] += d1.x * xb.x + d1.y * xb.y + d1.z * xb.z + d1.w * xb.w;
            accB[2] += d2.x * xb.x + d2.y * xb.y + d2.z * xb.z + d2.w * xb.w;
            accB[3] += d3.x * xb.x + d3.y * xb.y + d3.z * xb.z + d3.w * xb.w;
            accB[4] += e0.x * hb.x + e0.y * hb.y + e0.z * hb.z + e0.w * hb.w;
            accB[5] += e1.x * hb.x + e1.y * hb.y + e1.z * hb.z + e1.w * hb.w;
            accB[6] += e2.x * hb.x + e2.y * hb.y + e2.z * hb.z + e2.w * hb.w;
            accB[7] += e3.x * hb.x + e3.y * hb.y + e3.z * hb.z + e3.w * hb.w;
        }

        // warp-level reduce of 8 gate partials; no CTA barrier between rows
#pragma unroll
        for (int g = 0; g < 8; ++g) {
            float a = accA[g] + accB[g];
#pragma unroll
            for (int s = 16; s > 0; s >>= 1)
                a += __shfl_xor_sync(0xFFFFFFFFu, a, s);
            if (lane == 0) red[j][warp][g] = a;
        }
    }
    const int nrows = j;
    __syncthreads();

    // cross-warp totals: thread t -> (row j = t/8, gate g = t%8)
    if (tid < nrows * 8) {
        const int jj = tid >> 3;
        const int g  = tid & 7;
        float s = 0.0f;
#pragma unroll
        for (int w = 0; w < NWARP; ++w) s += red[jj][w][g];
        tot[jj][g] = s;
    }
    __syncthreads();

    // gating: thread j handles this CTA's j-th row
    if (tid < nrows) {
        const int r = blockIdx.x + tid * GRID;

        float i_t = tot[tid][0] + tot[tid][4] + __ldg(b_i + r);
        float f_t = tot[tid][1] + tot[tid][5] + __ldg(b_f + r);
        float o_t = tot[tid][2] + tot[tid][6] + __ldg(b_o + r);
        float z_t = tot[tid][3] + tot[tid][7] + __ldg(b_z + r);

        float mp = __ldg(m_prev + r);
        float cp = __ldg(c_prev + r);
        float np = __ldg(n_prev + r);

        // stable log_sigmoid(f) = min(f,0) - log1p(exp(-|f|))
        float log_f = fminf(f_t, 0.0f) - log1pf(expf(-fabsf(f_t)));
        float m_t = fmaxf(log_f + mp, i_t);
        float i_p = expf(i_t - m_t);
        float f_p = expf(log_f + mp - m_t);
        float c_t = f_p * cp + i_p * tanhf(z_t);
        float n_t = f_p * np + i_p;
        float sig_o = 1.0f / (1.0f + expf(-o_t));
        float h_t = sig_o * tanhf(c_t / n_t);

        out[r]            = h_t;
        out[HDIM + r]     = c_t;
        out[2 * HDIM + r] = n_t;
        out[3 * HDIM + r] = m_t;
    }
}

extern "C" void kernel_launch(void* const* d_in, const int* in_sizes, int n_in,
                              void* d_out, int out_size)
{
    const float* x      = (const float*)d_in[0];
    const float* h_prev = (const float*)d_in[1];
    const float* c_prev = (const float*)d_in[2];
    const float* n_prev = (const float*)d_in[3];
    const float* m_prev = (const float*)d_in[4];
    const float* w_i    = (const float*)d_in[5];
    const float* w_f    = (const float*)d_in[6];
    const float* w_o    = (const float*)d_in[7];
    const float* w_z    = (const float*)d_in[8];
    const float* r_i    = (const float*)d_in[9];
    const float* r_f    = (const float*)d_in[10];
    const float* r_o    = (const float*)d_in[11];
    const float* r_z    = (const float*)d_in[12];
    const float* b_i    = (const float*)d_in[13];
    const float* b_f    = (const float*)d_in[14];
    const float* b_o    = (const float*)d_in[15];
    const float* b_z    = (const float*)d_in[16];
    float* out = (float*)d_out;

    slstm_pers2_kernel<<<GRID, TPB>>>(x, h_prev, c_prev, n_prev, m_prev,
                                      w_i, w_f, w_o, w_z,
                                      r_i, r_f, r_o, r_z,
                                      b_i, b_f, b_o, b_z, out);
}

// round 5
// speedup vs baseline: 1.3037x; 1.0680x over previous
#include <cuda_runtime.h>
#include <math.h>

#define HDIM 4096
#define IDIM 4096
#define TPB  256
#define NWARP (TPB / 32)

__global__ __launch_bounds__(TPB, 2) void slstm_row_kernel(
    const float* __restrict__ x,
    const float* __restrict__ h_prev,
    const float* __restrict__ c_prev,
    const float* __restrict__ n_prev,
    const float* __restrict__ m_prev,
    const float* __restrict__ w_i,
    const float* __restrict__ w_f,
    const float* __restrict__ w_o,
    const float* __restrict__ w_z,
    const float* __restrict__ r_i,
    const float* __restrict__ r_f,
    const float* __restrict__ r_o,
    const float* __restrict__ r_z,
    const float* __restrict__ b_i,
    const float* __restrict__ b_f,
    const float* __restrict__ b_o,
    const float* __restrict__ b_z,
    float* __restrict__ out)
{
    const int row = blockIdx.x;
    const int tid = threadIdx.x;
    const int lane = tid & 31;
    const int warp = tid >> 5;

    const size_t roff = (size_t)row * IDIM;

    const float4* W0 = (const float4*)(w_i + roff);
    const float4* W1 = (const float4*)(w_f + roff);
    const float4* W2 = (const float4*)(w_o + roff);
    const float4* W3 = (const float4*)(w_z + roff);
    const float4* R0 = (const float4*)(r_i + roff);
    const float4* R1 = (const float4*)(r_f + roff);
    const float4* R2 = (const float4*)(r_o + roff);
    const float4* R3 = (const float4*)(r_z + roff);

    const float4* xv4 = (const float4*)x;
    const float4* hv4 = (const float4*)h_prev;

    // dual accumulator banks to break dependency chains
    float accA[8], accB[8];
#pragma unroll
    for (int g = 0; g < 8; ++g) { accA[g] = 0.0f; accB[g] = 0.0f; }

    // IDIM/4 = 1024 float4 / row; TPB=256 threads -> 4 k-slices, processed as
    // 2 blocks of 2 slices with all 20 loads front-batched per block.
    // launch_bounds(256,2) gives a 128-reg budget so the whole batch stays live.
#pragma unroll
    for (int blk = 0; blk < 2; ++blk) {
        const int ka = (2 * blk + 0) * TPB + tid;
        const int kb = (2 * blk + 1) * TPB + tid;

        // ---- front-batched loads (20 x LDG.128) ----
        float4 xa = __ldg(xv4 + ka);
        float4 ha = __ldg(hv4 + ka);
        float4 xb = __ldg(xv4 + kb);
        float4 hb = __ldg(hv4 + kb);

        float4 a0 = __ldcs(W0 + ka);
        float4 a1 = __ldcs(W1 + ka);
        float4 a2 = __ldcs(W2 + ka);
        float4 a3 = __ldcs(W3 + ka);
        float4 c0 = __ldcs(R0 + ka);
        float4 c1 = __ldcs(R1 + ka);
        float4 c2 = __ldcs(R2 + ka);
        float4 c3 = __ldcs(R3 + ka);

        float4 d0 = __ldcs(W0 + kb);
        float4 d1 = __ldcs(W1 + kb);
        float4 d2 = __ldcs(W2 + kb);
        float4 d3 = __ldcs(W3 + kb);
        float4 e0 = __ldcs(R0 + kb);
        float4 e1 = __ldcs(R1 + kb);
        float4 e2 = __ldcs(R2 + kb);
        float4 e3 = __ldcs(R3 + kb);

        // ---- compute phase ----
        accA[0] += a0.x * xa.x + a0.y * xa.y + a0.z * xa.z + a0.w * xa.w;
        accA[1] += a1.x * xa.x + a1.y * xa.y + a1.z * xa.z + a1.w * xa.w;
        accA[2] += a2.x * xa.x + a2.y * xa.y + a2.z * xa.z + a2.w * xa.w;
        accA[3] += a3.x * xa.x + a3.y * xa.y + a3.z * xa.z + a3.w * xa.w;
        accA[4] += c0.x * ha.x + c0.y * ha.y + c0.z * ha.z + c0.w * ha.w;
        accA[5] += c1.x * ha.x + c1.y * ha.y + c1.z * ha.z + c1.w * ha.w;
        accA[6] += c2.x * ha.x + c2.y * ha.y + c2.z * ha.z + c2.w * ha.w;
        accA[7] += c3.x * ha.x + c3.y * ha.y + c3.z * ha.z + c3.w * ha.w;

        accB[0] += d0.x * xb.x + d0.y * xb.y + d0.z * xb.z + d0.w * xb.w;
        accB[1] += d1.x * xb.x + d1.y * xb.y + d1.z * xb.z + d1.w * xb.w;
        accB[2] += d2.x * xb.x + d2.y * xb.y + d2.z * xb.z + d2.w * xb.w;
        accB[3] += d3.x * xb.x + d3.y * xb.y + d3.z * xb.z + d3.w * xb.w;
        accB[4] += e0.x * hb.x + e0.y * hb.y + e0.z * hb.z + e0.w * hb.w;
        accB[5] += e1.x * hb.x + e1.y * hb.y + e1.z * hb.z + e1.w * hb.w;
        accB[6] += e2.x * hb.x + e2.y * hb.y + e2.z * hb.z + e2.w * hb.w;
        accB[7] += e3.x * hb.x + e3.y * hb.y + e3.z * hb.z + e3.w * hb.w;
    }

    float acc[8];
#pragma unroll
    for (int g = 0; g < 8; ++g) acc[g] = accA[g] + accB[g];

    // warp reduction of 8 accumulators
#pragma unroll
    for (int g = 0; g < 8; ++g) {
#pragma unroll
        for (int s = 16; s > 0; s >>= 1)
            acc[g] += __shfl_xor_sync(0xFFFFFFFFu, acc[g], s);
    }

    __shared__ float red[NWARP][8];
    if (lane == 0) {
#pragma unroll
        for (int g = 0; g < 8; ++g) red[warp][g] = acc[g];
    }
    __syncthreads();

    if (warp == 0) {
        float tot = 0.0f;
        if (lane < 8) {
#pragma unroll
            for (int w = 0; w < NWARP; ++w) tot += red[w][lane];
        }
        float s_wi = __shfl_sync(0xFFFFFFFFu, tot, 0);
        float s_wf = __shfl_sync(0xFFFFFFFFu, tot, 1);
        float s_wo = __shfl_sync(0xFFFFFFFFu, tot, 2);
        float s_wz = __shfl_sync(0xFFFFFFFFu, tot, 3);
        float s_ri = __shfl_sync(0xFFFFFFFFu, tot, 4);
        float s_rf = __shfl_sync(0xFFFFFFFFu, tot, 5);
        float s_ro = __shfl_sync(0xFFFFFFFFu, tot, 6);
        float s_rz = __shfl_sync(0xFFFFFFFFu, tot, 7);

        if (lane == 0) {
            float i_t = s_wi + s_ri + __ldg(b_i + row);
            float f_t = s_wf + s_rf + __ldg(b_f + row);
            float o_t = s_wo + s_ro + __ldg(b_o + row);
            float z_t = s_wz + s_rz + __ldg(b_z + row);

            float mp = __ldg(m_prev + row);
            float cp = __ldg(c_prev + row);
            float np = __ldg(n_prev + row);

            // stable log_sigmoid(f) = min(f,0) - log1p(exp(-|f|))
            float log_f = fminf(f_t, 0.0f) - log1pf(expf(-fabsf(f_t)));
            float m_t = fmaxf(log_f + mp, i_t);
            float i_p = expf(i_t - m_t);
            float f_p = expf(log_f + mp - m_t);
            float c_t = f_p * cp + i_p * tanhf(z_t);
            float n_t = f_p * np + i_p;
            float sig_o = 1.0f / (1.0f + expf(-o_t));
            float h_t = sig_o * tanhf(c_t / n_t);

            out[row]            = h_t;
            out[HDIM + row]     = c_t;
            out[2 * HDIM + row] = n_t;
            out[3 * HDIM + row] = m_t;
        }
    }
}

extern "C" void kernel_launch(void* const* d_in, const int* in_sizes, int n_in,
                              void* d_out, int out_size)
{
    const float* x      = (const float*)d_in[0];
    const float* h_prev = (const float*)d_in[1];
    const float* c_prev = (const float*)d_in[2];
    const float* n_prev = (const float*)d_in[3];
    const float* m_prev = (const float*)d_in[4];
    const float* w_i    = (const float*)d_in[5];
    const float* w_f    = (const float*)d_in[6];
    const float* w_o    = (const float*)d_in[7];
    const float* w_z    = (const float*)d_in[8];
    const float* r_i    = (const float*)d_in[9];
    const float* r_f    = (const float*)d_in[10];
    const float* r_o    = (const float*)d_in[11];
    const float* r_z    = (const float*)d_in[12];
    const float* b_i    = (const float*)d_in[13];
    const float* b_f    = (const float*)d_in[14];
    const float* b_o    = (const float*)d_in[15];
    const float* b_z    = (const float*)d_in[16];
    float* out = (float*)d_out;

    slstm_row_kernel<<<HDIM, TPB>>>(x, h_prev, c_prev, n_prev, m_prev,
                                    w_i, w_f, w_o, w_z,
                                    r_i, r_f, r_o, r_z,
                                    b_i, b_f, b_o, b_z, out);
}

// round 6
// speedup vs baseline: 1.3091x; 1.0041x over previous
#include <cuda_runtime.h>
#include <math.h>

#define HDIM 4096
#define IDIM 4096
#define TPB  256
#define NWARP (TPB / 32)

__global__ __launch_bounds__(TPB, 3) void slstm_row_kernel(
    const float* __restrict__ x,
    const float* __restrict__ h_prev,
    const float* __restrict__ c_prev,
    const float* __restrict__ n_prev,
    const float* __restrict__ m_prev,
    const float* __restrict__ w_i,
    const float* __restrict__ w_f,
    const float* __restrict__ w_o,
    const float* __restrict__ w_z,
    const float* __restrict__ r_i,
    const float* __restrict__ r_f,
    const float* __restrict__ r_o,
    const float* __restrict__ r_z,
    const float* __restrict__ b_i,
    const float* __restrict__ b_f,
    const float* __restrict__ b_o,
    const float* __restrict__ b_z,
    float* __restrict__ out)
{
    const int row = blockIdx.x;
    const int tid = threadIdx.x;
    const int lane = tid & 31;
    const int warp = tid >> 5;

    const size_t roff = (size_t)row * IDIM;

    const float4* W0 = (const float4*)(w_i + roff);
    const float4* W1 = (const float4*)(w_f + roff);
    const float4* W2 = (const float4*)(w_o + roff);
    const float4* W3 = (const float4*)(w_z + roff);
    const float4* R0 = (const float4*)(r_i + roff);
    const float4* R1 = (const float4*)(r_f + roff);
    const float4* R2 = (const float4*)(r_o + roff);
    const float4* R3 = (const float4*)(r_z + roff);

    const float4* xv4 = (const float4*)x;
    const float4* hv4 = (const float4*)h_prev;

    // dual accumulator banks to break dependency chains
    float accA[8], accB[8];
#pragma unroll
    for (int g = 0; g < 8; ++g) { accA[g] = 0.0f; accB[g] = 0.0f; }

    // IDIM/4 = 1024 float4 / row; TPB=256 threads -> 4 k-slices, processed as
    // 2 blocks of 2 slices with 20 loads front-batched per block. At
    // launch_bounds(256,3) (~85 regs) ptxas splits this into ~12-14-deep
    // in-flight groups; the 3rd resident CTA covers reduce/ramp tails.
#pragma unroll
    for (int blk = 0; blk < 2; ++blk) {
        const int ka = (2 * blk + 0) * TPB + tid;
        const int kb = (2 * blk + 1) * TPB + tid;

        // ---- front-batched loads (20 x LDG.128) ----
        float4 xa = __ldg(xv4 + ka);
        float4 ha = __ldg(hv4 + ka);
        float4 xb = __ldg(xv4 + kb);
        float4 hb = __ldg(hv4 + kb);

        float4 a0 = __ldcs(W0 + ka);
        float4 a1 = __ldcs(W1 + ka);
        float4 a2 = __ldcs(W2 + ka);
        float4 a3 = __ldcs(W3 + ka);
        float4 c0 = __ldcs(R0 + ka);
        float4 c1 = __ldcs(R1 + ka);
        float4 c2 = __ldcs(R2 + ka);
        float4 c3 = __ldcs(R3 + ka);

        float4 d0 = __ldcs(W0 + kb);
        float4 d1 = __ldcs(W1 + kb);
        float4 d2 = __ldcs(W2 + kb);
        float4 d3 = __ldcs(W3 + kb);
        float4 e0 = __ldcs(R0 + kb);
        float4 e1 = __ldcs(R1 + kb);
        float4 e2 = __ldcs(R2 + kb);
        float4 e3 = __ldcs(R3 + kb);

        // ---- compute phase ----
        accA[0] += a0.x * xa.x + a0.y * xa.y + a0.z * xa.z + a0.w * xa.w;
        accA[1] += a1.x * xa.x + a1.y * xa.y + a1.z * xa.z + a1.w * xa.w;
        accA[2] += a2.x * xa.x + a2.y * xa.y + a2.z * xa.z + a2.w * xa.w;
        accA[3] += a3.x * xa.x + a3.y * xa.y + a3.z * xa.z + a3.w * xa.w;
        accA[4] += c0.x * ha.x + c0.y * ha.y + c0.z * ha.z + c0.w * ha.w;
        accA[5] += c1.x * ha.x + c1.y * ha.y + c1.z * ha.z + c1.w * ha.w;
        accA[6] += c2.x * ha.x + c2.y * ha.y + c2.z * ha.z + c2.w * ha.w;
        accA[7] += c3.x * ha.x + c3.y * ha.y + c3.z * ha.z + c3.w * ha.w;

        accB[0] += d0.x * xb.x + d0.y * xb.y + d0.z * xb.z + d0.w * xb.w;
        accB[1] += d1.x * xb.x + d1.y * xb.y + d1.z * xb.z + d1.w * xb.w;
        accB[2] += d2.x * xb.x + d2.y * xb.y + d2.z * xb.z + d2.w * xb.w;
        accB[3] += d3.x * xb.x + d3.y * xb.y + d3.z * xb.z + d3.w * xb.w;
        accB[4] += e0.x * hb.x + e0.y * hb.y + e0.z * hb.z + e0.w * hb.w;
        accB[5] += e1.x * hb.x + e1.y * hb.y + e1.z * hb.z + e1.w * hb.w;
        accB[6] += e2.x * hb.x + e2.y * hb.y + e2.z * hb.z + e2.w * hb.w;
        accB[7] += e3.x * hb.x + e3.y * hb.y + e3.z * hb.z + e3.w * hb.w;
    }

    float acc[8];
#pragma unroll
    for (int g = 0; g < 8; ++g) acc[g] = accA[g] + accB[g];

    // warp reduction of 8 accumulators
#pragma unroll
    for (int g = 0; g < 8; ++g) {
#pragma unroll
        for (int s = 16; s > 0; s >>= 1)
            acc[g] += __shfl_xor_sync(0xFFFFFFFFu, acc[g], s);
    }

    __shared__ float red[NWARP][8];
    if (lane == 0) {
#pragma unroll
        for (int g = 0; g < 8; ++g) red[warp][g] = acc[g];
    }
    __syncthreads();

    if (warp == 0) {
        float tot = 0.0f;
        if (lane < 8) {
#pragma unroll
            for (int w = 0; w < NWARP; ++w) tot += red[w][lane];
        }
        float s_wi = __shfl_sync(0xFFFFFFFFu, tot, 0);
        float s_wf = __shfl_sync(0xFFFFFFFFu, tot, 1);
        float s_wo = __shfl_sync(0xFFFFFFFFu, tot, 2);
        float s_wz = __shfl_sync(0xFFFFFFFFu, tot, 3);
        float s_ri = __shfl_sync(0xFFFFFFFFu, tot, 4);
        float s_rf = __shfl_sync(0xFFFFFFFFu, tot, 5);
        float s_ro = __shfl_sync(0xFFFFFFFFu, tot, 6);
        float s_rz = __shfl_sync(0xFFFFFFFFu, tot, 7);

        if (lane == 0) {
            float i_t = s_wi + s_ri + __ldg(b_i + row);
            float f_t = s_wf + s_rf + __ldg(b_f + row);
            float o_t = s_wo + s_ro + __ldg(b_o + row);
            float z_t = s_wz + s_rz + __ldg(b_z + row);

            float mp = __ldg(m_prev + row);
            float cp = __ldg(c_prev + row);
            float np = __ldg(n_prev + row);

            // stable log_sigmoid(f) = min(f,0) - log1p(exp(-|f|))
            float log_f = fminf(f_t, 0.0f) - log1pf(expf(-fabsf(f_t)));
            float m_t = fmaxf(log_f + mp, i_t);
            float i_p = expf(i_t - m_t);
            float f_p = expf(log_f + mp - m_t);
            float c_t = f_p * cp + i_p * tanhf(z_t);
            float n_t = f_p * np + i_p;
            float sig_o = 1.0f / (1.0f + expf(-o_t));
            float h_t = sig_o * tanhf(c_t / n_t);

            out[row]            = h_t;
            out[HDIM + row]     = c_t;
            out[2 * HDIM + row] = n_t;
            out[3 * HDIM + row] = m_t;
        }
    }
}

extern "C" void kernel_launch(void* const* d_in, const int* in_sizes, int n_in,
                              void* d_out, int out_size)
{
    const float* x      = (const float*)d_in[0];
    const float* h_prev = (const float*)d_in[1];
    const float* c_prev = (const float*)d_in[2];
    const float* n_prev = (const float*)d_in[3];
    const float* m_prev = (const float*)d_in[4];
    const float* w_i    = (const float*)d_in[5];
    const float* w_f    = (const float*)d_in[6];
    const float* w_o    = (const float*)d_in[7];
    const float* w_z    = (const float*)d_in[8];
    const float* r_i    = (const float*)d_in[9];
    const float* r_f    = (const float*)d_in[10];
    const float* r_o    = (const float*)d_in[11];
    const float* r_z    = (const float*)d_in[12];
    const float* b_i    = (const float*)d_in[13];
    const float* b_f    = (const float*)d_in[14];
    const float* b_o    = (const float*)d_in[15];
    const float* b_z    = (const float*)d_in[16];
    float* out = (float*)d_out;

    slstm_row_kernel<<<HDIM, TPB>>>(x, h_prev, c_prev, n_prev, m_prev,
                                    w_i, w_f, w_o, w_z,
                                    r_i, r_f, r_o, r_z,
                                    b_i, b_f, b_o, b_z, out);
}